// round 1
// baseline (speedup 1.0000x reference)
#include <cuda_runtime.h>
#include <math.h>

#define BATCHN 2
#define SEQ    2048
#define HIDDEN 1024
#define NH     16
#define HS     64
#define ROWS   (BATCHN * SEQ)     /* 4096 */
#define QKVN   (3 * HIDDEN)       /* 3072 */

/* Scratch: device globals (no allocations allowed anywhere). */
__device__ float g_qkv[(size_t)ROWS * QKVN];   /* 48 MB: [row][3072] = Q|K|V */
__device__ float g_av [(size_t)ROWS * HIDDEN]; /* 16 MB: attention output    */

/* ------------------------------------------------------------------ */
/* Register-blocked SGEMM with fused bias: C[M,N] = A[M,K]@B[K,N] + b */
/* BM=BN=128, BK=8, 256 threads, 8x8 microtile per thread.            */
/* M%128==0, N%128==0, K%8==0 guaranteed by problem shapes.           */
/* ------------------------------------------------------------------ */
__global__ __launch_bounds__(256)
void sgemm_bias_kernel(const float* __restrict__ A,
                       const float* __restrict__ B,
                       const float* __restrict__ bias,
                       float* __restrict__ C,
                       int M, int N, int K)
{
    __shared__ float As[8][128];
    __shared__ float Bs[8][128];

    const int tid = threadIdx.x;
    const int bm  = blockIdx.y * 128;
    const int bn  = blockIdx.x * 128;

    const int tx = tid & 15;   /* microtile col group */
    const int ty = tid >> 4;   /* microtile row group */

    float acc[8][8];
#pragma unroll
    for (int i = 0; i < 8; i++)
#pragma unroll
        for (int j = 0; j < 8; j++) acc[i][j] = 0.f;

    /* A tile loader: 128 rows x 8 cols, one float4 per thread */
    const int arow = tid >> 1;
    const int acol = (tid & 1) * 4;
    /* B tile loader: 8 rows x 128 cols, one float4 per thread */
    const int brow = tid >> 5;
    const int bcol = (tid & 31) * 4;

    const float* Aptr = A + (size_t)bm * K;
    const float* Bptr = B + bn;

    for (int k0 = 0; k0 < K; k0 += 8) {
        float4 a4 = *(const float4*)(Aptr + (size_t)arow * K + k0 + acol);
        As[acol + 0][arow] = a4.x;
        As[acol + 1][arow] = a4.y;
        As[acol + 2][arow] = a4.z;
        As[acol + 3][arow] = a4.w;
        *(float4*)&Bs[brow][bcol] =
            *(const float4*)(Bptr + (size_t)(k0 + brow) * N + bcol);
        __syncthreads();

#pragma unroll
        for (int kk = 0; kk < 8; kk++) {
            float ar[8], br[8];
            *(float4*)&ar[0] = *(const float4*)&As[kk][ty * 8];
            *(float4*)&ar[4] = *(const float4*)&As[kk][ty * 8 + 4];
            *(float4*)&br[0] = *(const float4*)&Bs[kk][tx * 8];
            *(float4*)&br[4] = *(const float4*)&Bs[kk][tx * 8 + 4];
#pragma unroll
            for (int i = 0; i < 8; i++)
#pragma unroll
                for (int j = 0; j < 8; j++)
                    acc[i][j] += ar[i] * br[j];
        }
        __syncthreads();
    }

#pragma unroll
    for (int i = 0; i < 8; i++) {
        const int row = bm + ty * 8 + i;
#pragma unroll
        for (int j = 0; j < 8; j += 4) {
            const int col = bn + tx * 8 + j;
            float4 v;
            v.x = acc[i][j + 0] + bias[col + 0];
            v.y = acc[i][j + 1] + bias[col + 1];
            v.z = acc[i][j + 2] + bias[col + 2];
            v.w = acc[i][j + 3] + bias[col + 3];
            *(float4*)(C + (size_t)row * N + col) = v;
        }
    }
}

/* ------------------------------------------------------------------ */
/* Flash attention (no mask): one thread == one query row.            */
/* Block = 64 query rows of one (batch, head); grid (32, 16, 2).      */
/* Online softmax state (m, l) thread-private -> no reductions.       */
/* K/V 64x64 tiles in smem, read as uniform-address (broadcast) LDS.  */
/* ------------------------------------------------------------------ */
__global__ __launch_bounds__(64)
void attn_kernel()
{
    const int h = blockIdx.y;
    const int b = blockIdx.z;
    const int t = threadIdx.x;                    /* 0..63 */
    const int row = b * SEQ + blockIdx.x * 64 + t;

    __shared__ float Ks[64][68];   /* +4 pad: conflict-free STS.128 */
    __shared__ float Vs[64][68];

    float q[64], O[64];
    const float* qp = g_qkv + (size_t)row * QKVN + h * HS;
#pragma unroll
    for (int i = 0; i < 16; i++) {
        float4 v = *(const float4*)(qp + i * 4);
        q[4 * i + 0] = v.x; q[4 * i + 1] = v.y;
        q[4 * i + 2] = v.z; q[4 * i + 3] = v.w;
    }
#pragma unroll
    for (int d = 0; d < 64; d++) O[d] = 0.f;

    float m = -1e30f, l = 0.f;

    const int lr = t >> 4;          /* loader row-in-group 0..3  */
    const int lc = (t & 15) * 4;    /* loader col 0,4,...,60     */

    for (int kt = 0; kt < SEQ / 64; kt++) {
        __syncthreads();
        const float* kbase = g_qkv + (size_t)(b * SEQ + kt * 64) * QKVN
                             + HIDDEN + h * HS;
        const float* vbase = kbase + HIDDEN;
#pragma unroll
        for (int c = 0; c < 16; c++) {
            const int r = c * 4 + lr;
            *(float4*)&Ks[r][lc] = *(const float4*)(kbase + (size_t)r * QKVN + lc);
            *(float4*)&Vs[r][lc] = *(const float4*)(vbase + (size_t)r * QKVN + lc);
        }
        __syncthreads();

#pragma unroll
        for (int cch = 0; cch < 2; cch++) {       /* 2 chunks of 32 keys */
            float sv[32];
            float mt = -1e30f;
#pragma unroll
            for (int j = 0; j < 32; j++) {
                const float4* kr = (const float4*)&Ks[cch * 32 + j][0];
                float s0 = 0.f, s1 = 0.f, s2 = 0.f, s3 = 0.f;
#pragma unroll
                for (int d4 = 0; d4 < 16; d4++) {
                    float4 k4 = kr[d4];
                    s0 += q[4 * d4 + 0] * k4.x;
                    s1 += q[4 * d4 + 1] * k4.y;
                    s2 += q[4 * d4 + 2] * k4.z;
                    s3 += q[4 * d4 + 3] * k4.w;
                }
                float s = ((s0 + s1) + (s2 + s3)) * 0.125f;  /* 1/sqrt(64) */
                sv[j] = s;
                mt = fmaxf(mt, s);
            }
            const float mnew = fmaxf(m, mt);
            const float corr = __expf(m - mnew);  /* first iter: exp(-huge)=0 */
            m = mnew;
            l *= corr;
#pragma unroll
            for (int d = 0; d < 64; d++) O[d] *= corr;
#pragma unroll
            for (int j = 0; j < 32; j++) {
                const float p = __expf(sv[j] - m);
                l += p;
                const float4* vr = (const float4*)&Vs[cch * 32 + j][0];
#pragma unroll
                for (int d4 = 0; d4 < 16; d4++) {
                    float4 v4 = vr[d4];
                    O[4 * d4 + 0] += p * v4.x;
                    O[4 * d4 + 1] += p * v4.y;
                    O[4 * d4 + 2] += p * v4.z;
                    O[4 * d4 + 3] += p * v4.w;
                }
            }
        }
    }

    const float inv = 1.f / l;
    float* op = g_av + (size_t)row * HIDDEN + h * HS;
#pragma unroll
    for (int i = 0; i < 16; i++) {
        float4 v;
        v.x = O[4 * i + 0] * inv; v.y = O[4 * i + 1] * inv;
        v.z = O[4 * i + 2] * inv; v.w = O[4 * i + 3] * inv;
        *(float4*)(op + i * 4) = v;
    }
}

/* ------------------------------------------------------------------ */
extern "C" void kernel_launch(void* const* d_in, const int* in_sizes, int n_in,
                              void* d_out, int out_size)
{
    const float* x    = (const float*)d_in[0];
    const float* Wqkv = (const float*)d_in[1];
    const float* bqkv = (const float*)d_in[2];
    const float* Wo   = (const float*)d_in[3];
    const float* bo   = (const float*)d_in[4];
    float* out = (float*)d_out;

    float *qkv_ptr, *av_ptr;
    cudaGetSymbolAddress((void**)&qkv_ptr, g_qkv);
    cudaGetSymbolAddress((void**)&av_ptr,  g_av);

    /* 1) QKV projection: [4096,1024] @ [1024,3072] + b */
    dim3 g1(QKVN / 128, ROWS / 128);
    sgemm_bias_kernel<<<g1, 256>>>(x, Wqkv, bqkv, qkv_ptr, ROWS, QKVN, HIDDEN);

    /* 2) Attention over all (batch, head, 64-row q tiles) */
    dim3 g2(SEQ / 64, NH, BATCHN);
    attn_kernel<<<g2, 64>>>();

    /* 3) Output projection: [4096,1024] @ [1024,1024] + b */
    dim3 g3(HIDDEN / 128, ROWS / 128);
    sgemm_bias_kernel<<<g3, 256>>>(av_ptr, Wo, bo, out, ROWS, HIDDEN, HIDDEN);
}

// round 4
// speedup vs baseline: 3.8038x; 3.8038x over previous
#include <cuda_runtime.h>
#include <math.h>
#include <cstdint>

#define HID   1024
#define QKVN  3072
#define SEQL  2048
#define NHEAD 16
#define HS    64
#define ROWS  4096   /* BATCH*SEQ */
#define ZALL  32     /* BATCH*NHEAD */

/* ---------------- scratch (fp32, tf32-rounded where noted) ------------- */
#define OFF_XT   0UL                         /* x rounded        16 MB */
#define OFF_WQT  (OFF_XT  + 16777216UL)      /* Wqkv rounded     12 MB */
#define OFF_WOT  (OFF_WQT + 12582912UL)      /* Wo rounded        4 MB */
#define OFF_QKV  (OFF_WOT + 4194304UL)       /* qkv (rounded)    48 MB */
#define OFF_SCF  (OFF_QKV + 50331648UL)      /* scores/probs    512 MB */
#define OFF_AV   (OFF_SCF + 536870912UL)     /* av (rounded)     16 MB */
#define SCRATCH_BYTES (OFF_AV + 16777216UL)

__device__ unsigned char g_scratch[SCRATCH_BYTES];

__device__ __forceinline__ uint32_t smem_u32(const void* p) {
    uint32_t a;
    asm("{ .reg .u64 t; cvta.to.shared.u64 t, %1; cvt.u32.u64 %0, t; }"
        : "=r"(a) : "l"(p));
    return a;
}

__device__ __forceinline__ float rna_tf32(float v) {
    uint32_t u;
    asm("cvt.rna.tf32.f32 %0, %1;" : "=r"(u) : "f"(v));
    return __uint_as_float(u);
}

#define MMA_TF32(d, a, b)                                                   \
    asm volatile("mma.sync.aligned.m16n8k8.row.col.f32.tf32.tf32.f32 "      \
        "{%0,%1,%2,%3}, {%4,%5,%6,%7}, {%8,%9}, {%0,%1,%2,%3};"             \
        : "+f"((d)[0]), "+f"((d)[1]), "+f"((d)[2]), "+f"((d)[3])            \
        : "r"((a)[0]), "r"((a)[1]), "r"((a)[2]), "r"((a)[3]),               \
          "r"((b)[0]), "r"((b)[1]))

#define CPASYNC16(saddr, gaddr)                                             \
    asm volatile("cp.async.cg.shared.global [%0], [%1], 16;"                \
                 :: "r"(saddr), "l"(gaddr))

/* ------------------------------------------------------------------ */
/* TF32 GEMM:  C = scale*(A @ op(B)) (+ bias[col])                    */
/* A[M,K] row-major (lda). TRANSB: B[N,K] K-major -> C=A@B^T.         */
/* else:  B[K,N] N-major. BM=128, BK=16, 256 thr, 2-stage cp.async.   */
/* Inputs must already be tf32-rounded. ROUND: round outputs to tf32. */
/* grid: (N/BN, M/128, Z); z -> zo=z/16, zi=z%16 batch offsets.       */
/* ------------------------------------------------------------------ */
template<int BN, bool TRANSB, bool ROUND>
__global__ void __launch_bounds__(256)
gemm_tf32(const float* __restrict__ A, long lda, long saO, long saI,
          const float* __restrict__ B, long ldb, long sbO, long sbI,
          float* __restrict__ C, long ldc, long scO, long scI,
          const float* __restrict__ bias, float scale, int nk)
{
    constexpr int NT = BN / 32;                 /* mma n-tiles per warp  */
    constexpr int BST = TRANSB ? 20 : (BN + 8); /* Bs row stride (fl32)  */
    constexpr int ASZ = 128 * 20;
    constexpr int BSZ = TRANSB ? (BN * 20) : (16 * (BN + 8));

    __shared__ float As[2][ASZ];
    __shared__ float Bs[2][BSZ];

    const int tid = threadIdx.x;
    const int wid = tid >> 5, lane = tid & 31;
    const int wm = wid & 1, wn = wid >> 1;      /* warps 2(m) x 4(n)     */
    const int g = lane >> 2, t = lane & 3;

    const long zo = blockIdx.z >> 4, zi = blockIdx.z & 15;
    const long bm = (long)blockIdx.y * 128, bn = (long)blockIdx.x * BN;
    const float* pA = A + zo * saO + zi * saI + bm * lda;
    const float* pB = B + zo * sbO + zi * sbI + (TRANSB ? bn * ldb : bn);

    const uint32_t sA = smem_u32(As), sB = smem_u32(Bs);

    float acc[4][NT][4];
#pragma unroll
    for (int i = 0; i < 4; i++)
#pragma unroll
        for (int j = 0; j < NT; j++)
#pragma unroll
            for (int r = 0; r < 4; r++) acc[i][j][r] = 0.f;

    auto stage = [&](int it, int buf) {
        const long k0 = (long)it * 16;
        /* A tile: 128 x 16 = 512 16B-chunks */
#pragma unroll
        for (int ch = tid; ch < 512; ch += 256) {
            const int r = ch >> 2, c4 = (ch & 3) << 2;
            const float* gp = pA + (long)r * lda + k0 + c4;
            CPASYNC16(sA + (uint32_t)(buf * ASZ + r * 20 + c4) * 4u, gp);
        }
        if (TRANSB) {
            /* B tile: BN x 16 */
#pragma unroll
            for (int ch = tid; ch < BN * 4; ch += 256) {
                const int n = ch >> 2, c4 = (ch & 3) << 2;
                const float* gp = pB + (long)n * ldb + k0 + c4;
                CPASYNC16(sB + (uint32_t)(buf * BSZ + n * 20 + c4) * 4u, gp);
            }
        } else {
            /* B tile: 16 x BN */
#pragma unroll
            for (int ch = tid; ch < BN * 4; ch += 256) {
                const int k = ch / (BN / 4), n4 = (ch % (BN / 4)) << 2;
                const float* gp = pB + (k0 + k) * ldb + n4;
                CPASYNC16(sB + (uint32_t)(buf * BSZ + k * (BN + 8) + n4) * 4u, gp);
            }
        }
        asm volatile("cp.async.commit_group;" ::: "memory");
    };

    stage(0, 0);
    const int last = nk - 1;
    for (int it = 0; it < nk; it++) {
        const int buf = it & 1;
        if (it < last) {
            stage(it + 1, buf ^ 1);
            asm volatile("cp.async.wait_group 1;" ::: "memory");
        } else {
            asm volatile("cp.async.wait_group 0;" ::: "memory");
        }
        __syncthreads();

#pragma unroll
        for (int ks = 0; ks < 2; ks++) {
            const int kb = ks * 8;
            uint32_t af[4][4];
#pragma unroll
            for (int mt = 0; mt < 4; mt++) {
                const int r = wm * 64 + mt * 16 + g;
                af[mt][0] = __float_as_uint(As[buf][r * 20 + kb + t]);
                af[mt][1] = __float_as_uint(As[buf][(r + 8) * 20 + kb + t]);
                af[mt][2] = __float_as_uint(As[buf][r * 20 + kb + t + 4]);
                af[mt][3] = __float_as_uint(As[buf][(r + 8) * 20 + kb + t + 4]);
            }
            uint32_t bf[NT][2];
#pragma unroll
            for (int nt = 0; nt < NT; nt++) {
                const int n = wn * (BN / 4) + nt * 8 + g;
                if (TRANSB) {
                    bf[nt][0] = __float_as_uint(Bs[buf][n * 20 + kb + t]);
                    bf[nt][1] = __float_as_uint(Bs[buf][n * 20 + kb + t + 4]);
                } else {
                    bf[nt][0] = __float_as_uint(Bs[buf][(kb + t) * BST + n]);
                    bf[nt][1] = __float_as_uint(Bs[buf][(kb + t + 4) * BST + n]);
                }
            }
#pragma unroll
            for (int mt = 0; mt < 4; mt++)
#pragma unroll
                for (int nt = 0; nt < NT; nt++)
                    MMA_TF32(acc[mt][nt], af[mt], bf[nt]);
        }
        __syncthreads();
    }

    /* epilogue */
    float* Cz = C + zo * scO + zi * scI;
#pragma unroll
    for (int mt = 0; mt < 4; mt++) {
        const long r = bm + wm * 64 + mt * 16 + g;
#pragma unroll
        for (int nt = 0; nt < NT; nt++) {
            const long c = bn + wn * (BN / 4) + nt * 8 + 2 * t;
            float v0 = acc[mt][nt][0] * scale, v1 = acc[mt][nt][1] * scale;
            float v2 = acc[mt][nt][2] * scale, v3 = acc[mt][nt][3] * scale;
            if (bias) {
                const float b0 = __ldg(bias + c), b1 = __ldg(bias + c + 1);
                v0 += b0; v1 += b1; v2 += b0; v3 += b1;
            }
            if (ROUND) {
                v0 = rna_tf32(v0); v1 = rna_tf32(v1);
                v2 = rna_tf32(v2); v3 = rna_tf32(v3);
            }
            float2 lo; lo.x = v0; lo.y = v1;
            float2 hi; hi.x = v2; hi.y = v3;
            *(float2*)(Cz + r * ldc + c) = lo;
            *(float2*)(Cz + (r + 8) * ldc + c) = hi;
        }
    }
}

/* ---------------- elementwise tf32 rounding ---------------- */
__global__ void round_kernel(const float4* __restrict__ in,
                             float4* __restrict__ out, long n4)
{
    const long i = (long)blockIdx.x * 256 + threadIdx.x;
    if (i >= n4) return;
    float4 v = in[i];
    v.x = rna_tf32(v.x); v.y = rna_tf32(v.y);
    v.z = rna_tf32(v.z); v.w = rna_tf32(v.w);
    out[i] = v;
}

/* ------- in-place row softmax (2048 fp32) -> tf32-rounded probs ------- */
__global__ void __launch_bounds__(256)
softmax_kernel(float* __restrict__ S)
{
    __shared__ float red[16];
    float* s = S + (size_t)blockIdx.x * SEQL;
    const int t = threadIdx.x;
    float v[8];
    *(float4*)&v[0] = *(const float4*)(s + t * 8);
    *(float4*)&v[4] = *(const float4*)(s + t * 8 + 4);

    float m = v[0];
#pragma unroll
    for (int i = 1; i < 8; i++) m = fmaxf(m, v[i]);
#pragma unroll
    for (int o = 16; o; o >>= 1) m = fmaxf(m, __shfl_xor_sync(0xffffffffu, m, o));
    if ((t & 31) == 0) red[t >> 5] = m;
    __syncthreads();
    float M = red[0];
#pragma unroll
    for (int i = 1; i < 8; i++) M = fmaxf(M, red[i]);

    float l = 0.f;
#pragma unroll
    for (int i = 0; i < 8; i++) { v[i] = __expf(v[i] - M); l += v[i]; }
#pragma unroll
    for (int o = 16; o; o >>= 1) l += __shfl_xor_sync(0xffffffffu, l, o);
    if ((t & 31) == 0) red[8 + (t >> 5)] = l;
    __syncthreads();
    float L = 0.f;
#pragma unroll
    for (int i = 0; i < 8; i++) L += red[8 + i];
    const float inv = 1.f / L;

    float4 o0, o1;
    o0.x = rna_tf32(v[0] * inv); o0.y = rna_tf32(v[1] * inv);
    o0.z = rna_tf32(v[2] * inv); o0.w = rna_tf32(v[3] * inv);
    o1.x = rna_tf32(v[4] * inv); o1.y = rna_tf32(v[5] * inv);
    o1.z = rna_tf32(v[6] * inv); o1.w = rna_tf32(v[7] * inv);
    *(float4*)(s + t * 8)     = o0;
    *(float4*)(s + t * 8 + 4) = o1;
}

/* ------------------------------------------------------------------ */
extern "C" void kernel_launch(void* const* d_in, const int* in_sizes, int n_in,
                              void* d_out, int out_size)
{
    const float* x    = (const float*)d_in[0];
    const float* Wqkv = (const float*)d_in[1];
    const float* bqkv = (const float*)d_in[2];
    const float* Wo   = (const float*)d_in[3];
    const float* bo   = (const float*)d_in[4];
    float* out = (float*)d_out;

    unsigned char* sc;
    cudaGetSymbolAddress((void**)&sc, g_scratch);
    float* xt  = (float*)(sc + OFF_XT);
    float* wqt = (float*)(sc + OFF_WQT);
    float* wot = (float*)(sc + OFF_WOT);
    float* qkv = (float*)(sc + OFF_QKV);
    float* scf = (float*)(sc + OFF_SCF);
    float* av  = (float*)(sc + OFF_AV);

    /* round inputs to tf32 */
    round_kernel<<<(ROWS * HID / 4 + 255) / 256, 256>>>(
        (const float4*)x, (float4*)xt, ROWS * HID / 4);
    round_kernel<<<(HID * QKVN / 4 + 255) / 256, 256>>>(
        (const float4*)Wqkv, (float4*)wqt, HID * QKVN / 4);
    round_kernel<<<(HID * HID / 4 + 255) / 256, 256>>>(
        (const float4*)Wo, (float4*)wot, HID * HID / 4);

    /* qkv = x @ Wqkv + b (output tf32-rounded: feeds Q/K/V MMAs) */
    gemm_tf32<128, false, true><<<dim3(QKVN / 128, ROWS / 128, 1), 256>>>(
        xt, HID, 0, 0, wqt, QKVN, 0, 0,
        qkv, QKVN, 0, 0, bqkv, 1.0f, HID / 16);

    /* scores[z] = Q @ K^T * 0.125 (fp32 out) */
    gemm_tf32<128, true, false><<<dim3(SEQL / 128, SEQL / 128, ZALL), 256>>>(
        qkv, QKVN, (long)SEQL * QKVN, 64,
        qkv + HID, QKVN, (long)SEQL * QKVN, 64,
        scf, SEQL, 16L * SEQL * SEQL, (long)SEQL * SEQL,
        nullptr, 0.125f, HS / 16);

    /* softmax rows in place (probs tf32-rounded) */
    softmax_kernel<<<ZALL * SEQL, 256>>>(scf);

    /* av[z] = P @ V (output tf32-rounded; scattered to [b][q][h*64+d]) */
    gemm_tf32<64, false, true><<<dim3(1, SEQL / 128, ZALL), 256>>>(
        scf, SEQL, 16L * SEQL * SEQL, (long)SEQL * SEQL,
        qkv + 2 * HID, QKVN, (long)SEQL * QKVN, 64,
        av, HID, (long)SEQL * HID, 64, nullptr, 1.0f, SEQL / 16);

    /* out = av @ Wo + b (fp32 out) */
    gemm_tf32<128, false, false><<<dim3(HID / 128, ROWS / 128, 1), 256>>>(
        av, HID, 0, 0, wot, HID, 0, 0,
        out, HID, 0, 0, bo, 1.0f, HID / 16);
}

// round 6
// speedup vs baseline: 9.7330x; 2.5588x over previous
#include <cuda_runtime.h>
#include <cuda_fp16.h>
#include <math.h>
#include <cstdint>

#define HID   1024
#define QKVN  3072
#define SEQL  2048
#define NHEAD 16
#define HS    64
#define ROWS  4096   /* BATCH*SEQ */
#define ZALL  32     /* BATCH*NHEAD */

/* ---------------- scratch layout (bytes) — 56 MB total ---------------- */
#define OFF_XH   0UL                          /* x fp16            8 MB */
#define OFF_WQT  (OFF_XH  + 8388608UL)        /* Wqkv^T fp16       6 MB */
#define OFF_WOT  (OFF_WQT + 6291456UL)        /* Wo^T fp16         2 MB */
#define OFF_QKVH (OFF_WOT + 2097152UL)        /* qkv fp16         24 MB */
#define OFF_VT   (OFF_QKVH + 25165824UL)      /* V^T per-z fp16    8 MB */
#define OFF_AVH  (OFF_VT  + 8388608UL)        /* av fp16           8 MB */
#define SCRATCH_BYTES (OFF_AVH + 8388608UL)

__device__ unsigned char g_scratch[SCRATCH_BYTES];

__device__ __forceinline__ uint32_t smem_u32(const void* p) {
    uint32_t a;
    asm("{ .reg .u64 t; cvta.to.shared.u64 t, %1; cvt.u32.u64 %0, t; }"
        : "=r"(a) : "l"(p));
    return a;
}

#define MMA_F16(d, a, b)                                                    \
    asm volatile("mma.sync.aligned.m16n8k16.row.col.f32.f16.f16.f32 "       \
        "{%0,%1,%2,%3}, {%4,%5,%6,%7}, {%8,%9}, {%0,%1,%2,%3};"             \
        : "+f"((d)[0]), "+f"((d)[1]), "+f"((d)[2]), "+f"((d)[3])            \
        : "r"((a)[0]), "r"((a)[1]), "r"((a)[2]), "r"((a)[3]),               \
          "r"((b)[0]), "r"((b)[1]))

#define CPASYNC16(saddr, gaddr)                                             \
    asm volatile("cp.async.cg.shared.global [%0], [%1], 16;"                \
                 :: "r"(saddr), "l"(gaddr))

__device__ __forceinline__ uint32_t h2u(__half2 v) {
    return *(uint32_t*)&v;
}

/* ------------------------------------------------------------------ */
/* fp16 GEMM: C = scale*(A @ B^T) (+ bias[col])  — as Round-4 layout  */
/* A[M,K] K-major fp16 (lda), B[N,K] K-major fp16 (ldb).              */
/* BM=128, BK=32, 256 thr, 3-buffer cp.async, 1 barrier per K-iter.   */
/* ------------------------------------------------------------------ */
template<int BN, bool OUTF16>
__global__ void __launch_bounds__(256)
gemm_h(const __half* __restrict__ A, long lda,
       const __half* __restrict__ B, long ldb,
       void* __restrict__ Cv, long ldc,
       const float* __restrict__ bias, float scale, int nk)
{
    constexpr int NT  = BN / 32;
    constexpr int AST = 40;
    constexpr int ASZ = 128 * AST;
    constexpr int BSZ = BN * AST;

    extern __shared__ __half sm[];
    __half* As = sm;
    __half* Bs = sm + 3 * ASZ;

    const int tid = threadIdx.x;
    const int wid = tid >> 5, lane = tid & 31;
    const int wm = wid & 1, wn = wid >> 1;
    const int g = lane >> 2, t = lane & 3;

    const long bm = (long)blockIdx.y * 128, bn = (long)blockIdx.x * BN;
    const __half* pA = A + bm * lda;
    const __half* pB = B + bn * ldb;

    const uint32_t sA = smem_u32(As), sB = smem_u32(Bs);

    float acc[4][NT][4];
#pragma unroll
    for (int i = 0; i < 4; i++)
#pragma unroll
        for (int j = 0; j < NT; j++)
#pragma unroll
            for (int r = 0; r < 4; r++) acc[i][j][r] = 0.f;

    auto stage = [&](int it, int buf) {
        const long k0 = (long)it * 32;
#pragma unroll
        for (int ch = tid; ch < 512; ch += 256) {
            const int r = ch >> 2, c8 = (ch & 3) * 8;
            CPASYNC16(sA + (uint32_t)(buf * ASZ + r * AST + c8) * 2u,
                      pA + (long)r * lda + k0 + c8);
        }
#pragma unroll
        for (int ch = tid; ch < BN * 4; ch += 256) {
            const int n = ch >> 2, c8 = (ch & 3) * 8;
            CPASYNC16(sB + (uint32_t)(buf * BSZ + n * AST + c8) * 2u,
                      pB + (long)n * ldb + k0 + c8);
        }
        asm volatile("cp.async.commit_group;" ::: "memory");
    };

    stage(0, 0);
    if (nk > 1) stage(1, 1);

    for (int it = 0; it < nk; it++) {
        if (it == nk - 1) {
            asm volatile("cp.async.wait_group 0;" ::: "memory");
        } else {
            asm volatile("cp.async.wait_group 1;" ::: "memory");
        }
        __syncthreads();
        if (it + 2 < nk) stage(it + 2, (it + 2) % 3);

        const int buf = it % 3;
        const __half* Ab = As + buf * ASZ;
        const __half* Bb = Bs + buf * BSZ;
#pragma unroll
        for (int ks = 0; ks < 2; ks++) {
            const int kb = ks * 16;
            uint32_t af[4][4];
#pragma unroll
            for (int mt = 0; mt < 4; mt++) {
                const int r = wm * 64 + mt * 16 + g;
                af[mt][0] = *(const uint32_t*)(Ab + r * AST + kb + 2 * t);
                af[mt][1] = *(const uint32_t*)(Ab + (r + 8) * AST + kb + 2 * t);
                af[mt][2] = *(const uint32_t*)(Ab + r * AST + kb + 2 * t + 8);
                af[mt][3] = *(const uint32_t*)(Ab + (r + 8) * AST + kb + 2 * t + 8);
            }
            uint32_t bf[NT][2];
#pragma unroll
            for (int nt = 0; nt < NT; nt++) {
                const int n = wn * (BN / 4) + nt * 8 + g;
                bf[nt][0] = *(const uint32_t*)(Bb + n * AST + kb + 2 * t);
                bf[nt][1] = *(const uint32_t*)(Bb + n * AST + kb + 2 * t + 8);
            }
#pragma unroll
            for (int mt = 0; mt < 4; mt++)
#pragma unroll
                for (int nt = 0; nt < NT; nt++)
                    MMA_F16(acc[mt][nt], af[mt], bf[nt]);
        }
        __syncthreads();
    }

    float*  Cf = (float*)Cv;
    __half* Ch = (__half*)Cv;
#pragma unroll
    for (int mt = 0; mt < 4; mt++) {
        const long r = bm + wm * 64 + mt * 16 + g;
#pragma unroll
        for (int nt = 0; nt < NT; nt++) {
            const long c = bn + wn * (BN / 4) + nt * 8 + 2 * t;
            float v0 = acc[mt][nt][0] * scale, v1 = acc[mt][nt][1] * scale;
            float v2 = acc[mt][nt][2] * scale, v3 = acc[mt][nt][3] * scale;
            if (bias) {
                const float b0 = __ldg(bias + c), b1 = __ldg(bias + c + 1);
                v0 += b0; v1 += b1; v2 += b0; v3 += b1;
            }
            if (OUTF16) {
                *(__half2*)(Ch + r * ldc + c)       = __floats2half2_rn(v0, v1);
                *(__half2*)(Ch + (r + 8) * ldc + c) = __floats2half2_rn(v2, v3);
            } else {
                float2 lo; lo.x = v0; lo.y = v1;
                float2 hi; hi.x = v2; hi.y = v3;
                *(float2*)(Cf + r * ldc + c)       = lo;
                *(float2*)(Cf + (r + 8) * ldc + c) = hi;
            }
        }
    }
}

/* ------------------------------------------------------------------ */
/* Flash attention: 128 q-rows/CTA, 8 warps x 16 rows, Bc=64 keys.    */
/* Online softmax; P fragments taken straight from S accumulators.    */
/* grid: (SEQL/128, ZALL).  z -> b=z>>4, h=z&15.                      */
/* ------------------------------------------------------------------ */
__global__ void __launch_bounds__(256)
flash_kernel(const __half* __restrict__ qkvh, const __half* __restrict__ vt,
             __half* __restrict__ avh)
{
    __shared__ __half Ks[2][64 * 72];
    __shared__ __half Vs[2][64 * 72];

    const int tid = threadIdx.x, wid = tid >> 5, lane = tid & 31;
    const int g = lane >> 2, t = lane & 3;
    const int z = blockIdx.y, b = z >> 4, h = z & 15;
    const long q0 = (long)b * SEQL + (long)blockIdx.x * 128;

    const uint32_t sK = smem_u32(Ks), sV = smem_u32(Vs);
    const __half* Kg = qkvh + (long)b * SEQL * QKVN + HID + h * 64;
    const __half* Vg = vt + (long)z * HS * SEQL;

    /* Q fragments, pre-scaled by 1/8 (exact in fp16) */
    uint32_t qf[4][4];
    {
        const __half2 sc = __float2half2_rn(0.125f);
        const __half* q_r0 = qkvh + (q0 + wid * 16 + g) * QKVN + h * 64;
        const __half* q_r1 = q_r0 + 8 * QKVN;
#pragma unroll
        for (int kk = 0; kk < 4; kk++) {
            qf[kk][0] = h2u(__hmul2(*(const __half2*)(q_r0 + 16 * kk + 2 * t), sc));
            qf[kk][1] = h2u(__hmul2(*(const __half2*)(q_r1 + 16 * kk + 2 * t), sc));
            qf[kk][2] = h2u(__hmul2(*(const __half2*)(q_r0 + 16 * kk + 8 + 2 * t), sc));
            qf[kk][3] = h2u(__hmul2(*(const __half2*)(q_r1 + 16 * kk + 8 + 2 * t), sc));
        }
    }

    auto stage = [&](int it, int buf) {
        const long kv0 = (long)it * 64;
#pragma unroll
        for (int ch = tid; ch < 512; ch += 256) {
            const int r = ch >> 3, c8 = (ch & 7) * 8;
            CPASYNC16(sK + (uint32_t)(buf * 4608 + r * 72 + c8) * 2u,
                      Kg + (kv0 + r) * QKVN + c8);
            CPASYNC16(sV + (uint32_t)(buf * 4608 + r * 72 + c8) * 2u,
                      Vg + (long)r * SEQL + kv0 + c8);
        }
        asm volatile("cp.async.commit_group;" ::: "memory");
    };

    float Ot[8][4];
#pragma unroll
    for (int j = 0; j < 8; j++)
#pragma unroll
        for (int r = 0; r < 4; r++) Ot[j][r] = 0.f;
    float m0 = -1e30f, m1 = -1e30f, l0 = 0.f, l1 = 0.f;

    stage(0, 0);

    for (int it = 0; it < SEQL / 64; it++) {
        if (it < SEQL / 64 - 1) {
            stage(it + 1, (it + 1) & 1);
            asm volatile("cp.async.wait_group 1;" ::: "memory");
        } else {
            asm volatile("cp.async.wait_group 0;" ::: "memory");
        }
        __syncthreads();

        const __half* Kb = Ks[it & 1];
        const __half* Vb = Vs[it & 1];

        /* S = (Q/8) @ K^T : 16 x 64 per warp */
        float sacc[8][4];
#pragma unroll
        for (int j = 0; j < 8; j++)
#pragma unroll
            for (int r = 0; r < 4; r++) sacc[j][r] = 0.f;
#pragma unroll
        for (int kk = 0; kk < 4; kk++) {
            uint32_t bf[8][2];
#pragma unroll
            for (int j = 0; j < 8; j++) {
                const __half* kp = Kb + (8 * j + g) * 72 + 16 * kk + 2 * t;
                bf[j][0] = *(const uint32_t*)kp;
                bf[j][1] = *(const uint32_t*)(kp + 8);
            }
#pragma unroll
            for (int j = 0; j < 8; j++)
                MMA_F16(sacc[j], qf[kk], bf[j]);
        }

        /* online softmax */
        float mx0 = -1e30f, mx1 = -1e30f;
#pragma unroll
        for (int j = 0; j < 8; j++) {
            mx0 = fmaxf(mx0, fmaxf(sacc[j][0], sacc[j][1]));
            mx1 = fmaxf(mx1, fmaxf(sacc[j][2], sacc[j][3]));
        }
        mx0 = fmaxf(mx0, __shfl_xor_sync(0xffffffffu, mx0, 1));
        mx0 = fmaxf(mx0, __shfl_xor_sync(0xffffffffu, mx0, 2));
        mx1 = fmaxf(mx1, __shfl_xor_sync(0xffffffffu, mx1, 1));
        mx1 = fmaxf(mx1, __shfl_xor_sync(0xffffffffu, mx1, 2));

        const float mn0 = fmaxf(m0, mx0), mn1 = fmaxf(m1, mx1);
        const float c0 = __expf(m0 - mn0), c1 = __expf(m1 - mn1);
        m0 = mn0; m1 = mn1;
        l0 *= c0; l1 *= c1;
#pragma unroll
        for (int j = 0; j < 8; j++) {
            Ot[j][0] *= c0; Ot[j][1] *= c0;
            Ot[j][2] *= c1; Ot[j][3] *= c1;
        }

        uint32_t pf[4][4];
#pragma unroll
        for (int j = 0; j < 8; j++) {
            const float p0 = __expf(sacc[j][0] - m0);
            const float p1 = __expf(sacc[j][1] - m0);
            const float p2 = __expf(sacc[j][2] - m1);
            const float p3 = __expf(sacc[j][3] - m1);
            l0 += p0 + p1; l1 += p2 + p3;
            const int kk = j >> 1, hi = (j & 1) * 2;
            pf[kk][hi]     = h2u(__floats2half2_rn(p0, p1));
            pf[kk][hi + 1] = h2u(__floats2half2_rn(p2, p3));
        }

        /* O += P @ V : B operand from V^T tile (d-major rows) */
#pragma unroll
        for (int kk = 0; kk < 4; kk++) {
            uint32_t vb[8][2];
#pragma unroll
            for (int j = 0; j < 8; j++) {
                const __half* vp = Vb + (8 * j + g) * 72 + 16 * kk + 2 * t;
                vb[j][0] = *(const uint32_t*)vp;
                vb[j][1] = *(const uint32_t*)(vp + 8);
            }
#pragma unroll
            for (int j = 0; j < 8; j++)
                MMA_F16(Ot[j], pf[kk], vb[j]);
        }
        __syncthreads();
    }

    /* finalize: reduce l over quad, normalize, write av fp16 */
    l0 += __shfl_xor_sync(0xffffffffu, l0, 1);
    l0 += __shfl_xor_sync(0xffffffffu, l0, 2);
    l1 += __shfl_xor_sync(0xffffffffu, l1, 1);
    l1 += __shfl_xor_sync(0xffffffffu, l1, 2);
    const float i0 = 1.f / l0, i1 = 1.f / l1;

    __half* o_r0 = avh + (q0 + wid * 16 + g) * HID + h * 64;
    __half* o_r1 = o_r0 + 8 * HID;
#pragma unroll
    for (int j = 0; j < 8; j++) {
        *(__half2*)(o_r0 + 8 * j + 2 * t) =
            __floats2half2_rn(Ot[j][0] * i0, Ot[j][1] * i0);
        *(__half2*)(o_r1 + 8 * j + 2 * t) =
            __floats2half2_rn(Ot[j][2] * i1, Ot[j][3] * i1);
    }
}

/* ---------------- fp32 -> fp16 elementwise ---------------- */
__global__ void tohalf_kernel(const float4* __restrict__ in,
                              __half2* __restrict__ out, long n4)
{
    const long i = (long)blockIdx.x * 256 + threadIdx.x;
    if (i >= n4) return;
    float4 v = in[i];
    out[2 * i]     = __floats2half2_rn(v.x, v.y);
    out[2 * i + 1] = __floats2half2_rn(v.z, v.w);
}

/* -------- transpose fp32 [R][C] -> fp16 [C][R] (weights) -------- */
__global__ void trw_kernel(const float* __restrict__ in, long ldin,
                           __half* __restrict__ out, long ldout)
{
    __shared__ float tile[32][33];
    const int r0 = blockIdx.x * 32, c0 = blockIdx.y * 32;
    const int tx = threadIdx.x, ty = threadIdx.y;
#pragma unroll
    for (int k = 0; k < 4; k++)
        tile[ty + 8 * k][tx] = in[(long)(r0 + ty + 8 * k) * ldin + c0 + tx];
    __syncthreads();
#pragma unroll
    for (int k = 0; k < 4; k++)
        out[(long)(c0 + ty + 8 * k) * ldout + r0 + tx] =
            __float2half(tile[tx][ty + 8 * k]);
}

/* -------- per-z fp16 transpose: vt[z][d][s] = qkv_V[z][s][d] -------- */
__global__ void trh_kernel(const __half* __restrict__ in, long ldin,
                           long siO, long siI,
                           __half* __restrict__ out, long ldout, long soZ)
{
    __shared__ __half tile[32][33];
    const long zo = blockIdx.z >> 4, zi = blockIdx.z & 15;
    const __half* src = in + zo * siO + zi * siI;
    const int r0 = blockIdx.x * 32, c0 = blockIdx.y * 32;
    const int tx = threadIdx.x, ty = threadIdx.y;
#pragma unroll
    for (int k = 0; k < 4; k++)
        tile[ty + 8 * k][tx] = src[(long)(r0 + ty + 8 * k) * ldin + c0 + tx];
    __syncthreads();
    __half* dst = out + (long)blockIdx.z * soZ;
#pragma unroll
    for (int k = 0; k < 4; k++)
        dst[(long)(c0 + ty + 8 * k) * ldout + r0 + tx] = tile[tx][ty + 8 * k];
}

/* ------------------------------------------------------------------ */
extern "C" void kernel_launch(void* const* d_in, const int* in_sizes, int n_in,
                              void* d_out, int out_size)
{
    const float* x    = (const float*)d_in[0];
    const float* Wqkv = (const float*)d_in[1];
    const float* bqkv = (const float*)d_in[2];
    const float* Wo   = (const float*)d_in[3];
    const float* bo   = (const float*)d_in[4];
    float* out = (float*)d_out;

    unsigned char* sc;
    cudaGetSymbolAddress((void**)&sc, g_scratch);
    __half* xh   = (__half*)(sc + OFF_XH);
    __half* wqt  = (__half*)(sc + OFF_WQT);
    __half* wot  = (__half*)(sc + OFF_WOT);
    __half* qkvh = (__half*)(sc + OFF_QKVH);
    __half* vt   = (__half*)(sc + OFF_VT);
    __half* avh  = (__half*)(sc + OFF_AVH);

    const int smem128 = 3 * (128 * 40 + 128 * 40) * 2;  /* 61440 B */
    cudaFuncSetAttribute(gemm_h<128, true>,
                         cudaFuncAttributeMaxDynamicSharedMemorySize, smem128);
    cudaFuncSetAttribute(gemm_h<128, false>,
                         cudaFuncAttributeMaxDynamicSharedMemorySize, smem128);

    /* prep: x -> fp16; Wqkv^T, Wo^T -> fp16 K-major */
    tohalf_kernel<<<(ROWS * HID / 4 + 255) / 256, 256>>>(
        (const float4*)x, (__half2*)xh, ROWS * HID / 4);
    trw_kernel<<<dim3(HID / 32, QKVN / 32), dim3(32, 8)>>>(Wqkv, QKVN, wqt, HID);
    trw_kernel<<<dim3(HID / 32, HID / 32), dim3(32, 8)>>>(Wo, HID, wot, HID);

    /* qkv = x @ Wqkv + b -> fp16 [4096][3072] */
    gemm_h<128, true><<<dim3(QKVN / 128, ROWS / 128), 256, smem128>>>(
        xh, HID, wqt, HID, qkvh, QKVN, bqkv, 1.0f, HID / 32);

    /* vt[z][d][s] from V slice of qkv */
    trh_kernel<<<dim3(SEQL / 32, HS / 32, ZALL), dim3(32, 8)>>>(
        qkvh + 2 * HID, QKVN, (long)SEQL * QKVN, 64,
        vt, SEQL, (long)HS * SEQL);

    /* fused attention -> avh [4096][1024] (head-interleaved) */
    flash_kernel<<<dim3(SEQL / 128, ZALL), 256>>>(qkvh, vt, avh);

    /* out = av @ Wo + b -> fp32 */
    gemm_h<128, false><<<dim3(HID / 128, ROWS / 128), 256, smem128>>>(
        avh, HID, wot, HID, out, HID, bo, 1.0f, HID / 32);
}

// round 7
// speedup vs baseline: 10.6622x; 1.0955x over previous
#include <cuda_runtime.h>
#include <cuda_fp16.h>
#include <math.h>
#include <cstdint>

#define HID   1024
#define QKVN  3072
#define SEQL  2048
#define NHEAD 16
#define HS    64
#define ROWS  4096   /* BATCH*SEQ */
#define ZALL  32     /* BATCH*NHEAD */

/* ---------------- scratch layout (bytes) — 48 MB total ---------------- */
#define OFF_XH   0UL                          /* x fp16            8 MB */
#define OFF_WQT  (OFF_XH  + 8388608UL)        /* Wqkv^T fp16       6 MB */
#define OFF_WOT  (OFF_WQT + 6291456UL)        /* Wo^T fp16         2 MB */
#define OFF_QKVH (OFF_WOT + 2097152UL)        /* qkv fp16         24 MB */
#define OFF_AVH  (OFF_QKVH + 25165824UL)      /* av fp16           8 MB */
#define SCRATCH_BYTES (OFF_AVH + 8388608UL)

__device__ unsigned char g_scratch[SCRATCH_BYTES];

__device__ __forceinline__ uint32_t smem_u32(const void* p) {
    uint32_t a;
    asm("{ .reg .u64 t; cvta.to.shared.u64 t, %1; cvt.u32.u64 %0, t; }"
        : "=r"(a) : "l"(p));
    return a;
}

#define MMA_F16(d, a, b)                                                    \
    asm volatile("mma.sync.aligned.m16n8k16.row.col.f32.f16.f16.f32 "       \
        "{%0,%1,%2,%3}, {%4,%5,%6,%7}, {%8,%9}, {%0,%1,%2,%3};"             \
        : "+f"((d)[0]), "+f"((d)[1]), "+f"((d)[2]), "+f"((d)[3])            \
        : "r"((a)[0]), "r"((a)[1]), "r"((a)[2]), "r"((a)[3]),               \
          "r"((b)[0]), "r"((b)[1]))

#define CPASYNC16(saddr, gaddr)                                             \
    asm volatile("cp.async.cg.shared.global [%0], [%1], 16;"                \
                 :: "r"(saddr), "l"(gaddr))

#define LDSM4(d0, d1, d2, d3, a)                                            \
    asm volatile("ldmatrix.sync.aligned.m8n8.x4.shared.b16 {%0,%1,%2,%3}, [%4];" \
        : "=r"(d0), "=r"(d1), "=r"(d2), "=r"(d3) : "r"(a))

#define LDSM4T(d0, d1, d2, d3, a)                                           \
    asm volatile("ldmatrix.sync.aligned.m8n8.x4.trans.shared.b16 {%0,%1,%2,%3}, [%4];" \
        : "=r"(d0), "=r"(d1), "=r"(d2), "=r"(d3) : "r"(a))

__device__ __forceinline__ uint32_t h2u(__half2 v) { return *(uint32_t*)&v; }

/* ------------------------------------------------------------------ */
/* fp16 GEMM: C = scale*(A @ B^T) (+ bias[col])                       */
/* A[M,K] K-major fp16 (lda), B[N,K] K-major fp16 (ldb).              */
/* BM=128, BN=128, BK=32, 256 thr, 3-stage cp.async, 1 barrier/iter,  */
/* ldmatrix.x4 fragment loads.                                        */
/* ------------------------------------------------------------------ */
template<bool OUTF16>
__global__ void __launch_bounds__(256)
gemm_h(const __half* __restrict__ A, long lda,
       const __half* __restrict__ B, long ldb,
       void* __restrict__ Cv, long ldc,
       const float* __restrict__ bias, float scale, int nk)
{
    constexpr int BN  = 128;
    constexpr int NT  = 4;
    constexpr int AST = 40;        /* halves per smem row (32 + 8 pad) */
    constexpr int ASZ = 128 * AST;
    constexpr int BSZ = BN * AST;

    extern __shared__ __half sm[];
    __half* As = sm;               /* [3][ASZ] */
    __half* Bs = sm + 3 * ASZ;     /* [3][BSZ] */

    const int tid = threadIdx.x;
    const int wid = tid >> 5, lane = tid & 31;
    const int wm = wid & 1, wn = wid >> 1;
    const int g = lane >> 2, t = lane & 3;
    const int lrow = lane & 7, lg1 = (lane >> 3) & 1, lg2 = lane >> 4;

    const long bm = (long)blockIdx.y * 128, bn = (long)blockIdx.x * BN;
    const __half* pA = A + bm * lda;
    const __half* pB = B + bn * ldb;

    const uint32_t sA = smem_u32(As), sB = smem_u32(Bs);

    /* per-lane ldmatrix base addresses (bytes, buf/ks added later) */
    uint32_t aoff[4], boff[2];
#pragma unroll
    for (int mt = 0; mt < 4; mt++)
        aoff[mt] = sA + (uint32_t)((wm * 64 + mt * 16 + lg1 * 8 + lrow) * AST
                                   + lg2 * 8) * 2u;
#pragma unroll
    for (int p = 0; p < 2; p++)
        boff[p] = sB + (uint32_t)((wn * 32 + p * 16 + lg2 * 8 + lrow) * AST
                                  + lg1 * 8) * 2u;

    float acc[4][NT][4];
#pragma unroll
    for (int i = 0; i < 4; i++)
#pragma unroll
        for (int j = 0; j < NT; j++)
#pragma unroll
            for (int r = 0; r < 4; r++) acc[i][j][r] = 0.f;

    auto stage = [&](int it, int buf) {
        const long k0 = (long)it * 32;
#pragma unroll
        for (int ch = tid; ch < 512; ch += 256) {
            const int r = ch >> 2, c8 = (ch & 3) * 8;
            CPASYNC16(sA + (uint32_t)(buf * ASZ + r * AST + c8) * 2u,
                      pA + (long)r * lda + k0 + c8);
        }
#pragma unroll
        for (int ch = tid; ch < 512; ch += 256) {
            const int n = ch >> 2, c8 = (ch & 3) * 8;
            CPASYNC16(sB + (uint32_t)(buf * BSZ + n * AST + c8) * 2u,
                      pB + (long)n * ldb + k0 + c8);
        }
        asm volatile("cp.async.commit_group;" ::: "memory");
    };

    stage(0, 0);
    if (nk > 1) stage(1, 1);

    for (int it = 0; it < nk; it++) {
        if (it == nk - 1) {
            asm volatile("cp.async.wait_group 0;" ::: "memory");
        } else {
            asm volatile("cp.async.wait_group 1;" ::: "memory");
        }
        __syncthreads();
        if (it + 2 < nk) stage(it + 2, (it + 2) % 3);

        const uint32_t aB = (uint32_t)((it % 3) * ASZ) * 2u;
        const uint32_t bB = (uint32_t)((it % 3) * BSZ) * 2u;
#pragma unroll
        for (int ks = 0; ks < 2; ks++) {
            const uint32_t ko = (uint32_t)ks * 32u;   /* 16 halves */
            uint32_t af[4][4];
#pragma unroll
            for (int mt = 0; mt < 4; mt++)
                LDSM4(af[mt][0], af[mt][1], af[mt][2], af[mt][3],
                      aoff[mt] + aB + ko);
            uint32_t bf[NT][2];
#pragma unroll
            for (int p = 0; p < 2; p++)
                LDSM4(bf[2 * p][0], bf[2 * p][1], bf[2 * p + 1][0],
                      bf[2 * p + 1][1], boff[p] + bB + ko);
#pragma unroll
            for (int mt = 0; mt < 4; mt++)
#pragma unroll
                for (int nt = 0; nt < NT; nt++)
                    MMA_F16(acc[mt][nt], af[mt], bf[nt]);
        }
        /* no trailing barrier: next iteration's top barrier fences reuse */
    }

    float*  Cf = (float*)Cv;
    __half* Ch = (__half*)Cv;
#pragma unroll
    for (int mt = 0; mt < 4; mt++) {
        const long r = bm + wm * 64 + mt * 16 + g;
#pragma unroll
        for (int nt = 0; nt < NT; nt++) {
            const long c = bn + wn * 32 + nt * 8 + 2 * t;
            float v0 = acc[mt][nt][0] * scale, v1 = acc[mt][nt][1] * scale;
            float v2 = acc[mt][nt][2] * scale, v3 = acc[mt][nt][3] * scale;
            if (bias) {
                const float b0 = __ldg(bias + c), b1 = __ldg(bias + c + 1);
                v0 += b0; v1 += b1; v2 += b0; v3 += b1;
            }
            if (OUTF16) {
                *(__half2*)(Ch + r * ldc + c)       = __floats2half2_rn(v0, v1);
                *(__half2*)(Ch + (r + 8) * ldc + c) = __floats2half2_rn(v2, v3);
            } else {
                float2 lo; lo.x = v0; lo.y = v1;
                float2 hi; hi.x = v2; hi.y = v3;
                *(float2*)(Cf + r * ldc + c)       = lo;
                *(float2*)(Cf + (r + 8) * ldc + c) = hi;
            }
        }
    }
}

/* ------------------------------------------------------------------ */
/* Flash attention: 128 q-rows/CTA, 8 warps x 16 rows, Bc=64 keys.    */
/* K and V staged straight from qkv; V fragments via ldmatrix.trans.  */
/* 3-stage cp.async, 1 barrier per KV tile.                           */
/* grid: (SEQL/128, ZALL).  z -> b=z>>4, h=z&15.                      */
/* ------------------------------------------------------------------ */
#define FTS 4608   /* halves per K (or V) stage: 64 * 72 */

__global__ void __launch_bounds__(256)
flash_kernel(const __half* __restrict__ qkvh, __half* __restrict__ avh)
{
    extern __shared__ __half fsm[];
    __half* Ks = fsm;            /* [3][FTS] */
    __half* Vs = fsm + 3 * FTS;  /* [3][FTS] */

    const int tid = threadIdx.x, wid = tid >> 5, lane = tid & 31;
    const int g = lane >> 2, t = lane & 3;
    const int lrow = lane & 7, lg1 = (lane >> 3) & 1, lg2 = lane >> 4;
    const int z = blockIdx.y, b = z >> 4, h = z & 15;
    const long q0 = (long)b * SEQL + (long)blockIdx.x * 128;

    const uint32_t sK = smem_u32(Ks), sV = smem_u32(Vs);
    const __half* Kg = qkvh + (long)b * SEQL * QKVN + HID + h * 64;
    const __half* Vg = Kg + HID;

    /* Q fragments, pre-scaled by 1/8 (exact in fp16) */
    uint32_t qf[4][4];
    {
        const __half2 sc = __float2half2_rn(0.125f);
        const __half* q_r0 = qkvh + (q0 + wid * 16 + g) * QKVN + h * 64;
        const __half* q_r1 = q_r0 + 8 * QKVN;
#pragma unroll
        for (int kk = 0; kk < 4; kk++) {
            qf[kk][0] = h2u(__hmul2(*(const __half2*)(q_r0 + 16 * kk + 2 * t), sc));
            qf[kk][1] = h2u(__hmul2(*(const __half2*)(q_r1 + 16 * kk + 2 * t), sc));
            qf[kk][2] = h2u(__hmul2(*(const __half2*)(q_r0 + 16 * kk + 8 + 2 * t), sc));
            qf[kk][3] = h2u(__hmul2(*(const __half2*)(q_r1 + 16 * kk + 8 + 2 * t), sc));
        }
    }

    /* ldmatrix lane bases (bytes; buf/kk added later) */
    uint32_t kfoff[4], vfoff[4];
#pragma unroll
    for (int p = 0; p < 4; p++) {
        kfoff[p] = sK + (uint32_t)((p * 16 + lg2 * 8 + lrow) * 72 + lg1 * 8) * 2u;
        vfoff[p] = sV + (uint32_t)((lg1 * 8 + lrow) * 72 + (2 * p + lg2) * 8) * 2u;
    }

    auto stage = [&](int it, int buf) {
        const long kv0 = (long)it * 64;
#pragma unroll
        for (int ch = tid; ch < 512; ch += 256) {
            const int r = ch >> 3, c8 = (ch & 7) * 8;
            const long go = (kv0 + r) * QKVN + c8;
            CPASYNC16(sK + (uint32_t)(buf * FTS + r * 72 + c8) * 2u, Kg + go);
            CPASYNC16(sV + (uint32_t)(buf * FTS + r * 72 + c8) * 2u, Vg + go);
        }
        asm volatile("cp.async.commit_group;" ::: "memory");
    };

    float Ot[8][4];
#pragma unroll
    for (int j = 0; j < 8; j++)
#pragma unroll
        for (int r = 0; r < 4; r++) Ot[j][r] = 0.f;
    float m0 = -1e30f, m1 = -1e30f, l0 = 0.f, l1 = 0.f;

    stage(0, 0);
    stage(1, 1);

    for (int it = 0; it < SEQL / 64; it++) {
        if (it == SEQL / 64 - 1) {
            asm volatile("cp.async.wait_group 0;" ::: "memory");
        } else {
            asm volatile("cp.async.wait_group 1;" ::: "memory");
        }
        __syncthreads();
        if (it + 2 < SEQL / 64) stage(it + 2, (it + 2) % 3);

        const uint32_t kB = (uint32_t)((it % 3) * FTS) * 2u;

        /* S = (Q/8) @ K^T : 16 x 64 per warp */
        float sacc[8][4];
#pragma unroll
        for (int j = 0; j < 8; j++)
#pragma unroll
            for (int r = 0; r < 4; r++) sacc[j][r] = 0.f;
#pragma unroll
        for (int kk = 0; kk < 4; kk++) {
            uint32_t bf[8][2];
#pragma unroll
            for (int p = 0; p < 4; p++)
                LDSM4(bf[2 * p][0], bf[2 * p][1], bf[2 * p + 1][0],
                      bf[2 * p + 1][1], kfoff[p] + kB + kk * 32u);
#pragma unroll
            for (int j = 0; j < 8; j++)
                MMA_F16(sacc[j], qf[kk], bf[j]);
        }

        /* online softmax */
        float mx0 = -1e30f, mx1 = -1e30f;
#pragma unroll
        for (int j = 0; j < 8; j++) {
            mx0 = fmaxf(mx0, fmaxf(sacc[j][0], sacc[j][1]));
            mx1 = fmaxf(mx1, fmaxf(sacc[j][2], sacc[j][3]));
        }
        mx0 = fmaxf(mx0, __shfl_xor_sync(0xffffffffu, mx0, 1));
        mx0 = fmaxf(mx0, __shfl_xor_sync(0xffffffffu, mx0, 2));
        mx1 = fmaxf(mx1, __shfl_xor_sync(0xffffffffu, mx1, 1));
        mx1 = fmaxf(mx1, __shfl_xor_sync(0xffffffffu, mx1, 2));

        const float mn0 = fmaxf(m0, mx0), mn1 = fmaxf(m1, mx1);
        const float c0 = __expf(m0 - mn0), c1 = __expf(m1 - mn1);
        m0 = mn0; m1 = mn1;
        l0 *= c0; l1 *= c1;
#pragma unroll
        for (int j = 0; j < 8; j++) {
            Ot[j][0] *= c0; Ot[j][1] *= c0;
            Ot[j][2] *= c1; Ot[j][3] *= c1;
        }

        uint32_t pf[4][4];
#pragma unroll
        for (int j = 0; j < 8; j++) {
            const float p0 = __expf(sacc[j][0] - m0);
            const float p1 = __expf(sacc[j][1] - m0);
            const float p2 = __expf(sacc[j][2] - m1);
            const float p3 = __expf(sacc[j][3] - m1);
            l0 += p0 + p1; l1 += p2 + p3;
            const int kk = j >> 1, hi = (j & 1) * 2;
            pf[kk][hi]     = h2u(__floats2half2_rn(p0, p1));
            pf[kk][hi + 1] = h2u(__floats2half2_rn(p2, p3));
        }

        /* O += P @ V : V fragments via ldmatrix.trans on [key][d] tile */
#pragma unroll
        for (int kk = 0; kk < 4; kk++) {
            uint32_t vb[8][2];
#pragma unroll
            for (int p = 0; p < 4; p++)
                LDSM4T(vb[2 * p][0], vb[2 * p][1], vb[2 * p + 1][0],
                       vb[2 * p + 1][1], vfoff[p] + kB + kk * 2304u);
#pragma unroll
            for (int j = 0; j < 8; j++)
                MMA_F16(Ot[j], pf[kk], vb[j]);
        }
        /* no trailing barrier */
    }

    /* finalize: reduce l over quad, normalize, write av fp16 */
    l0 += __shfl_xor_sync(0xffffffffu, l0, 1);
    l0 += __shfl_xor_sync(0xffffffffu, l0, 2);
    l1 += __shfl_xor_sync(0xffffffffu, l1, 1);
    l1 += __shfl_xor_sync(0xffffffffu, l1, 2);
    const float i0 = 1.f / l0, i1 = 1.f / l1;

    __half* o_r0 = avh + (q0 + wid * 16 + g) * HID + h * 64;
    __half* o_r1 = o_r0 + 8 * HID;
#pragma unroll
    for (int j = 0; j < 8; j++) {
        *(__half2*)(o_r0 + 8 * j + 2 * t) =
            __floats2half2_rn(Ot[j][0] * i0, Ot[j][1] * i0);
        *(__half2*)(o_r1 + 8 * j + 2 * t) =
            __floats2half2_rn(Ot[j][2] * i1, Ot[j][3] * i1);
    }
}

/* ---------------- fp32 -> fp16 elementwise ---------------- */
__global__ void tohalf_kernel(const float4* __restrict__ in,
                              __half2* __restrict__ out, long n4)
{
    const long i = (long)blockIdx.x * 256 + threadIdx.x;
    if (i >= n4) return;
    float4 v = in[i];
    out[2 * i]     = __floats2half2_rn(v.x, v.y);
    out[2 * i + 1] = __floats2half2_rn(v.z, v.w);
}

/* -------- transpose fp32 [R][C] -> fp16 [C][R] (weights) -------- */
__global__ void trw_kernel(const float* __restrict__ in, long ldin,
                           __half* __restrict__ out, long ldout)
{
    __shared__ float tile[32][33];
    const int r0 = blockIdx.x * 32, c0 = blockIdx.y * 32;
    const int tx = threadIdx.x, ty = threadIdx.y;
#pragma unroll
    for (int k = 0; k < 4; k++)
        tile[ty + 8 * k][tx] = in[(long)(r0 + ty + 8 * k) * ldin + c0 + tx];
    __syncthreads();
#pragma unroll
    for (int k = 0; k < 4; k++)
        out[(long)(c0 + ty + 8 * k) * ldout + r0 + tx] =
            __float2half(tile[tx][ty + 8 * k]);
}

/* ------------------------------------------------------------------ */
extern "C" void kernel_launch(void* const* d_in, const int* in_sizes, int n_in,
                              void* d_out, int out_size)
{
    const float* x    = (const float*)d_in[0];
    const float* Wqkv = (const float*)d_in[1];
    const float* bqkv = (const float*)d_in[2];
    const float* Wo   = (const float*)d_in[3];
    const float* bo   = (const float*)d_in[4];
    float* out = (float*)d_out;

    unsigned char* sc;
    cudaGetSymbolAddress((void**)&sc, g_scratch);
    __half* xh   = (__half*)(sc + OFF_XH);
    __half* wqt  = (__half*)(sc + OFF_WQT);
    __half* wot  = (__half*)(sc + OFF_WOT);
    __half* qkvh = (__half*)(sc + OFF_QKVH);
    __half* avh  = (__half*)(sc + OFF_AVH);

    const int smemG = 3 * (128 * 40 + 128 * 40) * 2;  /* 61440 B */
    const int smemF = 6 * FTS * 2;                    /* 55296 B */
    cudaFuncSetAttribute(gemm_h<true>,
                         cudaFuncAttributeMaxDynamicSharedMemorySize, smemG);
    cudaFuncSetAttribute(gemm_h<false>,
                         cudaFuncAttributeMaxDynamicSharedMemorySize, smemG);
    cudaFuncSetAttribute(flash_kernel,
                         cudaFuncAttributeMaxDynamicSharedMemorySize, smemF);

    /* prep: x -> fp16; Wqkv^T, Wo^T -> fp16 K-major */
    tohalf_kernel<<<(ROWS * HID / 4 + 255) / 256, 256>>>(
        (const float4*)x, (__half2*)xh, ROWS * HID / 4);
    trw_kernel<<<dim3(HID / 32, QKVN / 32), dim3(32, 8)>>>(Wqkv, QKVN, wqt, HID);
    trw_kernel<<<dim3(HID / 32, HID / 32), dim3(32, 8)>>>(Wo, HID, wot, HID);

    /* qkv = x @ Wqkv + b -> fp16 [4096][3072] */
    gemm_h<true><<<dim3(QKVN / 128, ROWS / 128), 256, smemG>>>(
        xh, HID, wqt, HID, qkvh, QKVN, bqkv, 1.0f, HID / 32);

    /* fused attention -> avh [4096][1024] (head-interleaved) */
    flash_kernel<<<dim3(SEQL / 128, ZALL), 256, smemF>>>(qkvh, avh);

    /* out = av @ Wo + b -> fp32 */
    gemm_h<false><<<dim3(HID / 128, ROWS / 128), 256, smemG>>>(
        avh, HID, wot, HID, out, HID, bo, 1.0f, HID / 32);
}